// round 2
// baseline (speedup 1.0000x reference)
#include <cuda_runtime.h>
#include <cuda_bf16.h>

// OSD decoder: bs=128, n=128, k=64, t=2.
// One CTA per batch element, 128 threads.

#define N 128
#define K 64
#define LLRMAX 100.0f
#define NPAT 2080   // 64 singles + 2016 pairs (t=2)

__global__ __launch_bounds__(128, 1)
void osd_kernel(const float* __restrict__ llrs,
                const float* __restrict__ gm,
                float* __restrict__ out)
{
    const int b   = blockIdx.x;
    const int tid = threadIdx.x;

    __shared__ float sLLR[N];          // clipped llr by ORIGINAL index
    __shared__ float sKey[N];          // |llr| sort keys (permuted in-place)
    __shared__ int   sIdx[N];          // payload: original index -> idx_sort
    __shared__ unsigned long long rlo[K], rhi[K];  // GF(2) rows, bit j = sorted col j
    __shared__ int   sPiv[K];
    __shared__ int   sMark[N];
    __shared__ int   sMrb[N];          // idx_mrb (sorted-col indices)
    __shared__ float sLlrMrb[N];
    __shared__ int   sTot[N];          // idx_total (original col indices)
    __shared__ unsigned long long sProw[K];  // parity part of gm_mrb rows
    __shared__ unsigned char sU[K];
    __shared__ unsigned long long sCparSh;
    __shared__ float sSm[K], sSp[K];   // signed llr, MRB part / parity part
    __shared__ float redS[128];
    __shared__ int   redId[128];
    __shared__ int   sPivBC;
    __shared__ int   sBi, sBj;

    // ---- load + clip ----
    {
        float x = llrs[b * N + tid];
        x = fminf(fmaxf(x, -LLRMAX), LLRMAX);
        sLLR[tid] = x;
        sKey[tid] = fabsf(x);
        sIdx[tid] = tid;
    }
    __syncthreads();

    // ---- stable bitonic sort, descending by |llr|, ties -> lower index first ----
    for (int kk = 2; kk <= N; kk <<= 1) {
        for (int j = kk >> 1; j > 0; j >>= 1) {
            int ixj = tid ^ j;
            if (ixj > tid) {
                float ka = sKey[tid], kb = sKey[ixj];
                int   ia = sIdx[tid], ib = sIdx[ixj];
                bool up = ((tid & kk) == 0);
                // aFirst: element a belongs before b in the target order
                bool aFirst = (ka > kb) || (ka == kb && ia < ib);
                bool doSwap = up ? !aFirst : aFirst;
                if (doSwap) {
                    sKey[tid] = kb; sKey[ixj] = ka;
                    sIdx[tid] = ib; sIdx[ixj] = ia;
                }
            }
            __syncthreads();
        }
    }

    // ---- build bit-packed permuted generator rows ----
    if (tid < K) {
        unsigned long long lo = 0ull, hi = 0ull;
        const float* grow = gm + tid * N;
        #pragma unroll 4
        for (int j = 0; j < N; j++) {
            int c = sIdx[j];
            if (grow[c] != 0.0f) {
                if (j < 64) lo |= 1ull << j;
                else        hi |= 1ull << (j - 64);
            }
        }
        rlo[tid] = lo; rhi[tid] = hi;
    }
    __syncthreads();

    // ---- GF(2) Gaussian elimination (full reduction) ----
    for (int i = 0; i < K; i++) {
        if (tid == 0) {
            unsigned long long lo = rlo[i];
            int p = lo ? (__ffsll((long long)lo) - 1)
                       : (64 + __ffsll((long long)rhi[i]) - 1);
            sPiv[i] = p;
            sPivBC  = p;
        }
        __syncthreads();
        int p = sPivBC;
        if (tid < K && tid != i) {
            unsigned long long w = (p < 64) ? rlo[tid] : rhi[tid];
            if ((w >> (p & 63)) & 1ull) {
                rlo[tid] ^= rlo[i];
                rhi[tid] ^= rhi[i];
            }
        }
        __syncthreads();
    }

    // ---- idx_mrb: pivots first, then non-pivot columns ascending ----
    sMark[tid] = 0;
    __syncthreads();
    if (tid < K) sMark[sPiv[tid]] = 1;
    __syncthreads();
    if (tid < K) sMrb[tid] = sPiv[tid];
    if (tid == 0) {
        int cnt = K;
        for (int j = 0; j < N; j++)
            if (!sMark[j]) sMrb[cnt++] = j;
    }
    __syncthreads();

    // ---- gather llr_mrb / idx_total ----
    {
        int m = sMrb[tid];
        sLlrMrb[tid] = sLLR[sIdx[m]];
        sTot[tid]    = sIdx[m];
    }
    __syncthreads();

    // ---- parity bitsets of gm_mrb rows ----
    if (tid < K) {
        unsigned long long pr = 0ull;
        unsigned long long lo = rlo[tid], hi = rhi[tid];
        #pragma unroll 4
        for (int p = 0; p < 64; p++) {
            int c = sMrb[64 + p];
            unsigned long long bit = (c < 64) ? ((lo >> c) & 1ull)
                                              : ((hi >> (c - 64)) & 1ull);
            pr |= bit << p;
        }
        sProw[tid] = pr;
    }
    if (tid < K) sU[tid] = (sLlrMrb[tid] > 0.0f) ? 1 : 0;
    __syncthreads();

    // ---- base codeword parity part ----
    if (tid == 0) {
        unsigned long long cp = 0ull;
        for (int i = 0; i < K; i++)
            if (sU[i]) cp ^= sProw[i];
        sCparSh = cp;
    }
    __syncthreads();
    unsigned long long cpar = sCparSh;

    // ---- signed llr: sllr_j = llr_mrb_j * (1 - 2 c_j) ----
    {
        int j = tid;
        int cj = (j < 64) ? (int)sU[j] : (int)((cpar >> (j - 64)) & 1ull);
        float s = cj ? -sLlrMrb[j] : sLlrMrb[j];
        if (j < 64) sSm[j] = s;
        else        sSp[j - 64] = s;
    }
    __syncthreads();

    // ---- candidate search over 2080 patterns ----
    float vp[64];
    #pragma unroll
    for (int bb = 0; bb < 64; bb++) vp[bb] = sSp[bb];

    float bestS = 0.0f;   // base pattern score
    int   bestId = -1;    // -1 == base
    for (int id = tid; id < NPAT; id += 128) {
        unsigned long long m;
        float S;
        if (id < 64) {
            m = sProw[id];
            S = sSm[id];
        } else {
            int r = id - 64;
            int i = 0;
            while (r >= 63 - i) { r -= 63 - i; i++; }
            int jj = i + 1 + r;
            m = sProw[i] ^ sProw[jj];
            S = sSm[i] + sSm[jj];
        }
        #pragma unroll
        for (int bb = 0; bb < 64; bb++)
            S += ((m >> bb) & 1ull) ? vp[bb] : 0.0f;
        if (S > bestS) { bestS = S; bestId = id; }
    }
    redS[tid] = bestS;
    redId[tid] = bestId;
    __syncthreads();

    if (tid == 0) {
        float bS = redS[0]; int bI = redId[0];
        for (int t2 = 1; t2 < 128; t2++) {
            float s2 = redS[t2]; int i2 = redId[t2];
            if (s2 > bS || (s2 == bS && i2 < bI)) { bS = s2; bI = i2; }
        }
        int fi = -1, fj = -1;
        if (bI >= 0) {
            if (bI < 64) fi = bI;
            else {
                int r = bI - 64, i = 0;
                while (r >= 63 - i) { r -= 63 - i; i++; }
                fi = i; fj = i + 1 + r;
            }
        }
        sBi = fi; sBj = fj;
    }
    __syncthreads();

    // ---- emit best codeword, un-permuted ----
    {
        int j = tid;
        int fi = sBi, fj = sBj;
        int cj = (j < 64) ? (int)sU[j] : (int)((cpar >> (j - 64)) & 1ull);
        if (j < 64) {
            if (j == fi) cj ^= 1;
            if (j == fj) cj ^= 1;
        } else {
            int p = j - 64;
            if (fi >= 0) cj ^= (int)((sProw[fi] >> p) & 1ull);
            if (fj >= 0) cj ^= (int)((sProw[fj] >> p) & 1ull);
        }
        out[b * N + sTot[j]] = (float)cj;
    }
}

extern "C" void kernel_launch(void* const* d_in, const int* in_sizes, int n_in,
                              void* d_out, int out_size)
{
    const float* llrs = (const float*)d_in[0];
    const float* gm   = (const float*)d_in[1];
    float* out        = (float*)d_out;
    int bs = in_sizes[0] / N;   // 128
    osd_kernel<<<bs, 128>>>(llrs, gm, out);
}

// round 4
// speedup vs baseline: 1.7147x; 1.7147x over previous
#include <cuda_runtime.h>
#include <cuda_bf16.h>

#define N 128
#define K 64
#define LLRMAX 100.0f
#define NPAT 2080   // 64 singles + 2016 pairs (t=2)

typedef unsigned long long u64;
typedef unsigned int u32;

__device__ __forceinline__ u32 mono(float s) {
    u32 u = __float_as_uint(s);
    return (u & 0x80000000u) ? ~u : (u | 0x80000000u);
}

__global__ __launch_bounds__(128, 1)
void osd_kernel(const float* __restrict__ llrs,
                const float* __restrict__ gm,
                float* __restrict__ out)
{
    const int b    = blockIdx.x;
    const int tid  = threadIdx.x;
    const int lane = tid & 31;
    const int warp = tid >> 5;

    __shared__ float sLLR[N];        // clipped llr by ORIGINAL index
    __shared__ int   sIdxArr[N];     // idx_sort
    __shared__ u64   sP[K];          // packed P rows (original col order, bit c = gm[r][64+c])
    __shared__ u64   rloS[K], rhiS[K];   // GF(2) rows over sorted cols
    __shared__ int   sPivArr[K];
    __shared__ u64   sPmLo, sPmHi;       // pivot-column mask
    __shared__ int   sMrbS[N];
    __shared__ float sLlrMrbS[N];
    __shared__ int   sTotS[N];
    __shared__ u64   sProwS[K];          // parity part of reduced rows (mrb order)
    __shared__ unsigned char sUS[K];
    __shared__ u64   sCparPart[2];
    __shared__ float sSm[K];             // signed llr, MRB half
    __shared__ float sSpArr[K];          // signed llr, parity half
    __shared__ float sLUT[8 * 256];      // 8-bit chunk partial sums
    __shared__ u64   sRed[4];

    // ================= Phase A (parallel): warp0 loads+sorts, warps1-3 pack P =================
    if (warp == 0) {
        // load all 128 llrs (4 per lane), clip, store sLLR, build sort keys
        u64 key[4];
        #pragma unroll
        for (int s = 0; s < 4; s++) {
            int e = s * 32 + lane;
            float x = llrs[b * N + e];
            x = fminf(fmaxf(x, -LLRMAX), LLRMAX);
            sLLR[e] = x;
            u32 ab = __float_as_uint(fabsf(x));
            // ascending sort => descending |llr|, tie -> smaller original idx first
            key[s] = (((u64)(ab ^ 0xFFFFFFFFu)) << 8) | (u32)e;
        }
        // bitonic sort, ascending by key
        for (int k2 = 2; k2 <= 128; k2 <<= 1) {
            for (int j = k2 >> 1; j > 0; j >>= 1) {
                if (j >= 32) {
                    int d = j >> 5;  // 1 or 2
                    #pragma unroll
                    for (int s = 0; s < 4; s++) {
                        if ((s & d) == 0) {
                            int e = s * 32 + lane;
                            bool up = ((e & k2) == 0);
                            u64 a = key[s], c = key[s + d];
                            u64 mn = a < c ? a : c;
                            u64 mx = a < c ? c : a;
                            key[s]     = up ? mn : mx;
                            key[s + d] = up ? mx : mn;
                        }
                    }
                } else {
                    #pragma unroll
                    for (int s = 0; s < 4; s++) {
                        int e = s * 32 + lane;
                        u64 other = __shfl_xor_sync(0xFFFFFFFFu, key[s], j);
                        bool iAmLower = ((lane & j) == 0);
                        bool up = ((e & k2) == 0);
                        u64 mn = key[s] < other ? key[s] : other;
                        u64 mx = key[s] < other ? other : key[s];
                        key[s] = (up == iAmLower) ? mn : mx;
                    }
                }
            }
        }
        #pragma unroll
        for (int s = 0; s < 4; s++)
            sIdxArr[s * 32 + lane] = (int)(key[s] & 0xFF);
    } else {
        // warps 1-3: pack P rows (coalesced loads + ballot)
        int r0  = (warp == 1) ? 0 : (warp == 2) ? 22 : 43;
        int cnt = (warp == 1) ? 22 : 21;
        #pragma unroll 2
        for (int q = 0; q < cnt; q++) {
            int r = r0 + q;
            float f0 = gm[r * N + 64 + lane];
            float f1 = gm[r * N + 96 + lane];
            u32 b0 = __ballot_sync(0xFFFFFFFFu, f0 != 0.0f);
            u32 b1 = __ballot_sync(0xFFFFFFFFu, f1 != 0.0f);
            if (lane == 0) sP[r] = (u64)b0 | ((u64)b1 << 32);
        }
    }
    __syncthreads();   // bar1

    // ================= Phase B: build permuted rows (threads 0..63) =================
    if (tid < K) {
        u64 myP = sP[tid];
        u64 lo = 0ull, hi = 0ull;
        #pragma unroll 4
        for (int j = 0; j < N; j++) {
            int c = sIdxArr[j];             // LDS broadcast
            u64 bit = (c == tid) ? 1ull : ((c >= 64) ? ((myP >> (c - 64)) & 1ull) : 0ull);
            if (j < 64) lo |= bit << j;
            else        hi |= bit << (j - 64);
        }
        rloS[tid] = lo;
        rhiS[tid] = hi;
    }
    __syncthreads();   // bar2

    // ================= Phase C: GF(2) elimination (warp0, rows in regs) =================
    if (warp == 0) {
        u64 a0lo = rloS[lane],      a0hi = rhiS[lane];
        u64 a1lo = rloS[lane + 32], a1hi = rhiS[lane + 32];
        u64 pmLo = 0ull, pmHi = 0ull;
        for (int i = 0; i < K; i++) {
            int sl = i & 31;
            u64 plo, phi;
            if (i < 32) { plo = __shfl_sync(0xFFFFFFFFu, a0lo, sl);
                          phi = __shfl_sync(0xFFFFFFFFu, a0hi, sl); }
            else        { plo = __shfl_sync(0xFFFFFFFFu, a1lo, sl);
                          phi = __shfl_sync(0xFFFFFFFFu, a1hi, sl); }
            int p = plo ? (__ffsll((long long)plo) - 1)
                        : 64 + (__ffsll((long long)phi) - 1);
            if (lane == 0) {
                sPivArr[i] = p;
                if (p < 64) pmLo |= 1ull << p; else pmHi |= 1ull << (p - 64);
            }
            bool hit0 = (p < 64) ? ((a0lo >> p) & 1ull) : ((a0hi >> (p - 64)) & 1ull);
            if (hit0 && lane != i)        { a0lo ^= plo; a0hi ^= phi; }
            bool hit1 = (p < 64) ? ((a1lo >> p) & 1ull) : ((a1hi >> (p - 64)) & 1ull);
            if (hit1 && (lane + 32) != i) { a1lo ^= plo; a1hi ^= phi; }
        }
        rloS[lane] = a0lo;      rhiS[lane] = a0hi;
        rloS[lane + 32] = a1lo; rhiS[lane + 32] = a1hi;
        if (lane == 0) { sPmLo = pmLo; sPmHi = pmHi; }
    }
    __syncthreads();   // bar3

    // ================= Phase D: idx_mrb, gather llr_mrb / idx_total =================
    {
        int m;
        if (tid < K) {
            m = sPivArr[tid];
        } else {
            // (tid-64)-th zero bit of pivot mask, ascending
            int t = tid - K;
            u64 zlo = ~sPmLo, zhi = ~sPmHi;
            int nlo = __popcll(zlo);
            u64 x; int base;
            if (t < nlo) { x = zlo; base = 0; }
            else         { x = zhi; base = 64; t -= nlo; }
            int pos = 0;
            #pragma unroll
            for (int byteI = 0; byteI < 8; byteI++) {
                u32 bb = (u32)(x >> (byteI * 8)) & 0xFFu;
                int c = __popc(bb);
                if (t < c) {
                    while (t > 0) { bb &= bb - 1; t--; }
                    pos = byteI * 8 + (__ffs(bb) - 1);
                    break;
                }
                t -= c;
            }
            m = base + pos;
        }
        sMrbS[tid]    = m;
        int oc        = sIdxArr[m];
        sLlrMrbS[tid] = sLLR[oc];
        sTotS[tid]    = oc;
    }
    __syncthreads();   // bar4

    // ================= Phase E: parity rows, u, base parity (threads 0..63) =================
    if (tid < K) {
        u64 lo = rloS[tid], hi = rhiS[tid];
        u64 pr = 0ull;
        #pragma unroll 4
        for (int p = 0; p < 64; p++) {
            int c = sMrbS[64 + p];          // LDS broadcast
            u64 bit = (c < 64) ? ((lo >> c) & 1ull) : ((hi >> (c - 64)) & 1ull);
            pr |= bit << p;
        }
        sProwS[tid] = pr;
        int u = (sLlrMrbS[tid] > 0.0f) ? 1 : 0;
        sUS[tid] = (unsigned char)u;
        u64 val = u ? pr : 0ull;
        #pragma unroll
        for (int o = 16; o > 0; o >>= 1)
            val ^= __shfl_xor_sync(0xFFFFFFFFu, val, o);
        if (lane == 0) sCparPart[warp] = val;   // warp 0 or 1
    }
    __syncthreads();   // bar5

    u64 cpar = sCparPart[0] ^ sCparPart[1];

    // signed llr: sllr_j = llr_mrb_j * (1 - 2 c_j)
    {
        int j = tid;
        int cj = (j < 64) ? (int)sUS[j] : (int)((cpar >> (j - 64)) & 1ull);
        float s = cj ? -sLlrMrbS[j] : sLlrMrbS[j];
        if (j < 64) sSm[j] = s;
        else        sSpArr[j - 64] = s;
    }
    __syncthreads();   // bar6

    // ================= Phase F: build 8-bit LUT (8 chunks x 256 entries) =================
    #pragma unroll
    for (int e = 0; e < 16; e++) {
        int idx2 = tid + (e << 7);          // 0..2047, consecutive per lane
        int ci = idx2 >> 8;
        int v  = idx2 & 255;
        float s = 0.0f;
        #pragma unroll
        for (int bb = 0; bb < 8; bb++)
            if ((v >> bb) & 1) s += sSpArr[ci * 8 + bb];
        sLUT[idx2] = s;
    }
    __syncthreads();   // bar7

    // ================= Phase G: candidate search =================
    u64 bestKey = (((u64)mono(0.0f)) << 32) | (u32)(NPAT + 1);   // base: id=-1
    for (int id = tid; id < NPAT; id += 128) {
        u64 m; float S;
        if (id < 64) {
            m = sProwS[id];
            S = sSm[id];
        } else {
            int r = id - 64;
            int i = (int)((127.0f - sqrtf(16129.0f - 8.0f * (float)r)) * 0.5f);
            if (i < 0) i = 0; if (i > 62) i = 62;
            while (i * (127 - i) / 2 > r) i--;
            while ((i + 1) * (126 - i) / 2 <= r) i++;
            int jj = i + 1 + (r - i * (127 - i) / 2);
            m = sProwS[i] ^ sProwS[jj];
            S = sSm[i] + sSm[jj];
        }
        #pragma unroll
        for (int cc = 0; cc < 8; cc++)
            S += sLUT[(cc << 8) | ((int)(m >> (cc * 8)) & 0xFF)];
        u64 keyv = (((u64)mono(S)) << 32) | (u32)(NPAT - id);
        if (keyv > bestKey) bestKey = keyv;
    }
    // warp max-reduce
    #pragma unroll
    for (int o = 16; o > 0; o >>= 1) {
        u64 other = __shfl_xor_sync(0xFFFFFFFFu, bestKey, o);
        if (other > bestKey) bestKey = other;
    }
    if (lane == 0) sRed[warp] = bestKey;
    __syncthreads();   // bar8

    // ================= Phase H: decode winner + emit =================
    {
        u64 bk = sRed[0];
        #pragma unroll
        for (int w = 1; w < 4; w++) if (sRed[w] > bk) bk = sRed[w];
        int id = NPAT - (int)(bk & 0xFFFFFFFFull);   // -1 = base
        int fi = -1, fj = -1;
        if (id >= 0) {
            if (id < 64) fi = id;
            else {
                int r = id - 64, i = 0;
                while (r >= 63 - i) { r -= 63 - i; i++; }
                fi = i; fj = i + 1 + r;
            }
        }
        int j = tid;
        int cj = (j < 64) ? (int)sUS[j] : (int)((cpar >> (j - 64)) & 1ull);
        if (j < 64) {
            if (j == fi) cj ^= 1;
            if (j == fj) cj ^= 1;
        } else {
            int p = j - 64;
            if (fi >= 0) cj ^= (int)((sProwS[fi] >> p) & 1ull);
            if (fj >= 0) cj ^= (int)((sProwS[fj] >> p) & 1ull);
        }
        out[b * N + sTotS[j]] = (float)cj;
    }
}

extern "C" void kernel_launch(void* const* d_in, const int* in_sizes, int n_in,
                              void* d_out, int out_size)
{
    const float* llrs = (const float*)d_in[0];
    const float* gm   = (const float*)d_in[1];
    float* out        = (float*)d_out;
    int bs = in_sizes[0] / N;   // 128
    osd_kernel<<<bs, 128>>>(llrs, gm, out);
}

// round 5
// speedup vs baseline: 2.1907x; 1.2776x over previous
#include <cuda_runtime.h>
#include <cuda_bf16.h>

#define N 128
#define K 64
#define LLRMAX 100.0f
#define NPAT 2080   // 64 singles + 2016 pairs (t=2)

typedef unsigned long long u64;
typedef unsigned int u32;

__device__ __forceinline__ u32 mono(float s) {
    u32 u = __float_as_uint(s);
    return (u & 0x80000000u) ? ~u : (u | 0x80000000u);
}

__device__ __forceinline__ void decode_pair(int r, int& pi, int& pj) {
    int i = (int)((127.0f - sqrtf(16129.0f - 8.0f * (float)r)) * 0.5f);
    if (i < 0) i = 0; if (i > 62) i = 62;
    while (i * (127 - i) / 2 > r) i--;
    while ((i + 1) * (126 - i) / 2 <= r) i++;
    pi = i;
    pj = i + 1 + (r - i * (127 - i) / 2);
}

__global__ __launch_bounds__(256, 1)
void osd_kernel(const float* __restrict__ llrs,
                const float* __restrict__ gm,
                float* __restrict__ out)
{
    const int b    = blockIdx.x;
    const int tid  = threadIdx.x;
    const int lane = tid & 31;
    const int warp = tid >> 5;

    __shared__ float sLLR[N];
    __shared__ int   sIdxArr[N];
    __shared__ u64   sP[K];                // packed P rows (orig col order)
    __shared__ u64   rloS[K], rhiS[K];     // GF(2) rows over sorted cols
    __shared__ int   sPivArr[K];
    __shared__ u64   sPmLo, sPmHi;
    __shared__ int   sMrbS[N];
    __shared__ float sLlrMrbS[N];
    __shared__ int   sTotS[N];
    __shared__ u64   sPP[2][K];            // parity partials
    __shared__ u64   sProwS[K];
    __shared__ unsigned char sUS[K];
    __shared__ u64   sCparPart[2];
    __shared__ float sSm[K];
    __shared__ float sSpArr[K];
    __shared__ float sLUT[8 * 256];
    __shared__ u64   sRed[8];

    // ===== Phase A: warp0 sorts, warps1-7 pack P =====
    if (warp == 0) {
        u64 key[4];
        #pragma unroll
        for (int s = 0; s < 4; s++) {
            int e = s * 32 + lane;
            float x = llrs[b * N + e];
            x = fminf(fmaxf(x, -LLRMAX), LLRMAX);
            sLLR[e] = x;
            u32 ab = __float_as_uint(fabsf(x));
            key[s] = (((u64)(ab ^ 0xFFFFFFFFu)) << 8) | (u32)e;   // asc key => desc |llr|, stable
        }
        for (int k2 = 2; k2 <= 128; k2 <<= 1) {
            for (int j = k2 >> 1; j > 0; j >>= 1) {
                if (j >= 32) {
                    int d = j >> 5;
                    #pragma unroll
                    for (int s = 0; s < 4; s++) {
                        if ((s & d) == 0) {
                            int e = s * 32 + lane;
                            bool up = ((e & k2) == 0);
                            u64 a = key[s], c = key[s + d];
                            u64 mn = a < c ? a : c;
                            u64 mx = a < c ? c : a;
                            key[s]     = up ? mn : mx;
                            key[s + d] = up ? mx : mn;
                        }
                    }
                } else {
                    #pragma unroll
                    for (int s = 0; s < 4; s++) {
                        int e = s * 32 + lane;
                        u64 other = __shfl_xor_sync(0xFFFFFFFFu, key[s], j);
                        bool iAmLower = ((lane & j) == 0);
                        bool up = ((e & k2) == 0);
                        u64 mn = key[s] < other ? key[s] : other;
                        u64 mx = key[s] < other ? other : key[s];
                        key[s] = (up == iAmLower) ? mn : mx;
                    }
                }
            }
        }
        #pragma unroll
        for (int s = 0; s < 4; s++)
            sIdxArr[s * 32 + lane] = (int)(key[s] & 0xFF);
    } else {
        for (int r = warp - 1; r < K; r += 7) {
            float f0 = gm[r * N + 64 + lane];
            float f1 = gm[r * N + 96 + lane];
            u32 b0 = __ballot_sync(0xFFFFFFFFu, f0 != 0.0f);
            u32 b1 = __ballot_sync(0xFFFFFFFFu, f1 != 0.0f);
            if (lane == 0) sP[r] = (u64)b0 | ((u64)b1 << 32);
        }
    }
    __syncthreads();   // bar1

    // ===== Phase B: permuted rows, 2 threads per row =====
    if (tid < 128) {
        int row = tid & 63, half = tid >> 6;
        u64 myP = sP[row];
        u64 w = 0ull;
        int j0 = half << 6;
        #pragma unroll 4
        for (int jj = 0; jj < 64; jj++) {
            int c = sIdxArr[j0 + jj];
            u64 bit = (c == row) ? 1ull : ((c >= 64) ? ((myP >> (c - 64)) & 1ull) : 0ull);
            w |= bit << jj;
        }
        if (half == 0) rloS[row] = w; else rhiS[row] = w;
    }
    __syncthreads();   // bar2

    // ===== Phase C: GF(2) elimination (warp0, rows in regs) =====
    if (warp == 0) {
        u64 a0lo = rloS[lane],      a0hi = rhiS[lane];
        u64 a1lo = rloS[lane + 32], a1hi = rhiS[lane + 32];
        u64 pmLo = 0ull, pmHi = 0ull;
        for (int i = 0; i < K; i++) {
            int sl = i & 31;
            u64 plo, phi;
            if (i < 32) { plo = __shfl_sync(0xFFFFFFFFu, a0lo, sl);
                          phi = __shfl_sync(0xFFFFFFFFu, a0hi, sl); }
            else        { plo = __shfl_sync(0xFFFFFFFFu, a1lo, sl);
                          phi = __shfl_sync(0xFFFFFFFFu, a1hi, sl); }
            int p = plo ? (__ffsll((long long)plo) - 1)
                        : 64 + (__ffsll((long long)phi) - 1);
            if (lane == 0) {
                sPivArr[i] = p;
                if (p < 64) pmLo |= 1ull << p; else pmHi |= 1ull << (p - 64);
            }
            bool hit0 = (p < 64) ? ((a0lo >> p) & 1ull) : ((a0hi >> (p - 64)) & 1ull);
            if (hit0 && lane != i)        { a0lo ^= plo; a0hi ^= phi; }
            bool hit1 = (p < 64) ? ((a1lo >> p) & 1ull) : ((a1hi >> (p - 64)) & 1ull);
            if (hit1 && (lane + 32) != i) { a1lo ^= plo; a1hi ^= phi; }
        }
        rloS[lane] = a0lo;      rhiS[lane] = a0hi;
        rloS[lane + 32] = a1lo; rhiS[lane + 32] = a1hi;
        if (lane == 0) { sPmLo = pmLo; sPmHi = pmHi; }
    }
    __syncthreads();   // bar3

    // ===== Phase D: idx_mrb + gathers =====
    if (tid < 128) {
        int m;
        if (tid < K) {
            m = sPivArr[tid];
        } else {
            int t = tid - K;
            u64 zlo = ~sPmLo, zhi = ~sPmHi;
            int nlo = __popcll(zlo);
            u64 x; int base;
            if (t < nlo) { x = zlo; base = 0; }
            else         { x = zhi; base = 64; t -= nlo; }
            int pos = 0;
            #pragma unroll
            for (int byteI = 0; byteI < 8; byteI++) {
                u32 bb = (u32)(x >> (byteI * 8)) & 0xFFu;
                int c = __popc(bb);
                if (t < c) {
                    while (t > 0) { bb &= bb - 1; t--; }
                    pos = byteI * 8 + (__ffs(bb) - 1);
                    break;
                }
                t -= c;
            }
            m = base + pos;
        }
        sMrbS[tid]    = m;
        int oc        = sIdxArr[m];
        sLlrMrbS[tid] = sLLR[oc];
        sTotS[tid]    = oc;
    }
    __syncthreads();   // bar4

    // ===== Phase E1: parity partials (2 threads/row) + u =====
    if (tid < 128) {
        int row = tid & 63, half = tid >> 6;
        u64 lo = rloS[row], hi = rhiS[row];
        u64 pr = 0ull;
        int p0 = half << 5;
        #pragma unroll 4
        for (int q = 0; q < 32; q++) {
            int p = p0 + q;
            int c = sMrbS[64 + p];
            u64 bit = (c < 64) ? ((lo >> c) & 1ull) : ((hi >> (c - 64)) & 1ull);
            pr |= bit << p;
        }
        sPP[half][row] = pr;
        if (half == 0) sUS[row] = (sLlrMrbS[row] > 0.0f) ? 1 : 0;
    }
    __syncthreads();   // bar5

    // ===== Phase E2: combine + base parity (threads 0..63 = warps 0,1) =====
    if (tid < K) {
        u64 pr = sPP[0][tid] | sPP[1][tid];
        sProwS[tid] = pr;
        u64 val = sUS[tid] ? pr : 0ull;
        #pragma unroll
        for (int o = 16; o > 0; o >>= 1)
            val ^= __shfl_xor_sync(0xFFFFFFFFu, val, o);
        if (lane == 0) sCparPart[warp] = val;
    }
    __syncthreads();   // bar6

    u64 cpar = sCparPart[0] ^ sCparPart[1];

    // ===== signed llr =====
    if (tid < 128) {
        int j = tid;
        int cj = (j < 64) ? (int)sUS[j] : (int)((cpar >> (j - 64)) & 1ull);
        float s = cj ? -sLlrMrbS[j] : sLlrMrbS[j];
        if (j < 64) sSm[j] = s;
        else        sSpArr[j - 64] = s;
    }
    __syncthreads();   // bar7

    // ===== Phase F: 8-bit LUT =====
    #pragma unroll
    for (int e = 0; e < 8; e++) {
        int idx2 = tid + (e << 8);          // 0..2047
        int ci = idx2 >> 8;
        int v  = idx2 & 255;
        float s = 0.0f;
        #pragma unroll
        for (int bb = 0; bb < 8; bb++)
            if ((v >> bb) & 1) s += sSpArr[ci * 8 + bb];
        sLUT[idx2] = s;
    }
    __syncthreads();   // bar8

    // ===== Phase G: candidate search (contiguous chunks, incremental decode) =====
    int id, cnt;
    if (tid < 32) { id = tid * 9;            cnt = 9; }
    else          { id = 288 + (tid - 32) * 8; cnt = 8; }

    int pi = 0, pj = 0;
    if (id >= 64 && id < NPAT) decode_pair(id - 64, pi, pj);

    u64 bestKey = (((u64)mono(0.0f)) << 32) | (u32)(NPAT + 1);   // base codeword
    for (int e = 0; e < cnt && id < NPAT; e++) {
        u64 m; float S;
        if (id < 64) { m = sProwS[id];            S = sSm[id]; }
        else         { m = sProwS[pi] ^ sProwS[pj]; S = sSm[pi] + sSm[pj]; }
        #pragma unroll
        for (int cc = 0; cc < 8; cc++)
            S += sLUT[(cc << 8) | ((int)(m >> (cc * 8)) & 0xFF)];
        u64 keyv = (((u64)mono(S)) << 32) | (u32)(NPAT - id);
        if (keyv > bestKey) bestKey = keyv;
        // advance
        id++;
        if (id == 64)     { pi = 0; pj = 1; }
        else if (id > 64) { pj++; if (pj == 64) { pi++; pj = pi + 1; } }
    }
    #pragma unroll
    for (int o = 16; o > 0; o >>= 1) {
        u64 other = __shfl_xor_sync(0xFFFFFFFFu, bestKey, o);
        if (other > bestKey) bestKey = other;
    }
    if (lane == 0) sRed[warp] = bestKey;
    __syncthreads();   // bar9

    // ===== Phase H: decode winner + emit (threads 0..127) =====
    if (tid < 128) {
        u64 bk = sRed[0];
        #pragma unroll
        for (int w = 1; w < 8; w++) if (sRed[w] > bk) bk = sRed[w];
        int wid2 = NPAT - (int)(bk & 0xFFFFFFFFull);   // -1 = base
        int fi = -1, fj = -1;
        if (wid2 >= 0) {
            if (wid2 < 64) fi = wid2;
            else           decode_pair(wid2 - 64, fi, fj);
        }
        int j = tid;
        int cj = (j < 64) ? (int)sUS[j] : (int)((cpar >> (j - 64)) & 1ull);
        if (j < 64) {
            if (j == fi) cj ^= 1;
            if (j == fj) cj ^= 1;
        } else {
            int p = j - 64;
            if (fi >= 0) cj ^= (int)((sProwS[fi] >> p) & 1ull);
            if (fj >= 0) cj ^= (int)((sProwS[fj] >> p) & 1ull);
        }
        out[b * N + sTotS[j]] = (float)cj;
    }
}

extern "C" void kernel_launch(void* const* d_in, const int* in_sizes, int n_in,
                              void* d_out, int out_size)
{
    const float* llrs = (const float*)d_in[0];
    const float* gm   = (const float*)d_in[1];
    float* out        = (float*)d_out;
    int bs = in_sizes[0] / N;   // 128
    osd_kernel<<<bs, 256>>>(llrs, gm, out);
}

// round 6
// speedup vs baseline: 2.8579x; 1.3046x over previous
#include <cuda_runtime.h>
#include <cuda_bf16.h>

#define N 128
#define K 64
#define LLRMAX 100.0f
#define NPAT 2080   // 64 singles + 2016 pairs (t=2)

typedef unsigned long long u64;
typedef unsigned int u32;

__device__ __forceinline__ u32 mono(float s) {
    u32 u = __float_as_uint(s);
    return (u & 0x80000000u) ? ~u : (u | 0x80000000u);
}

__device__ __forceinline__ void decode_pair(int r, int& pi, int& pj) {
    int i = (int)((127.0f - sqrtf(16129.0f - 8.0f * (float)r)) * 0.5f);
    if (i < 0) i = 0; if (i > 62) i = 62;
    while (i * (127 - i) / 2 > r) i--;
    while ((i + 1) * (126 - i) / 2 <= r) i++;
    pi = i;
    pj = i + 1 + (r - i * (127 - i) / 2);
}

__global__ __launch_bounds__(256, 1)
void osd_kernel(const float* __restrict__ llrs,
                const float* __restrict__ gm,
                float* __restrict__ out)
{
    const int b    = blockIdx.x;
    const int tid  = threadIdx.x;
    const int lane = tid & 31;
    const int warp = tid >> 5;

    __shared__ __align__(16) float sLLR[N];
    __shared__ __align__(16) u64   sKey[N];
    __shared__ __align__(16) int   sIdxArr[N];
    __shared__ unsigned short sRP[2][N];     // rank partials
    __shared__ u64   sP[K];                  // packed P rows (orig col order)
    __shared__ u64   rloS[K], rhiS[K];       // GF(2) rows over sorted cols
    __shared__ int   sPivArr[K];
    __shared__ u64   sPmLo, sPmHi;
    __shared__ __align__(16) int sMrbS[N];
    __shared__ float sLlrMrbS[N];
    __shared__ int   sTotS[N];
    __shared__ u64   sPP[2][K];              // parity partials
    __shared__ u64   sProwS[K];
    __shared__ unsigned char sUS[K];
    __shared__ u64   sCparPart[2];
    __shared__ float sSm[K];
    __shared__ float sLUT[8 * 256];
    __shared__ u64   sRed[8];

    // ===== Phase A: t<128 load llr + keys; warps 4-7 pack P =====
    if (tid < 128) {
        float x = llrs[b * N + tid];
        x = fminf(fmaxf(x, -LLRMAX), LLRMAX);
        sLLR[tid] = x;
        u32 ab = __float_as_uint(fabsf(x));
        // ascending key => descending |llr|, tie -> smaller original idx
        sKey[tid] = (((u64)(ab ^ 0xFFFFFFFFu)) << 8) | (u32)tid;
    }
    if (warp >= 4) {
        int r0 = (warp - 4) << 4;
        #pragma unroll 4
        for (int q = 0; q < 16; q++) {
            int r = r0 + q;
            float f0 = gm[r * N + 64 + lane];
            float f1 = gm[r * N + 96 + lane];
            u32 b0 = __ballot_sync(0xFFFFFFFFu, f0 != 0.0f);
            u32 b1 = __ballot_sync(0xFFFFFFFFu, f1 != 0.0f);
            if (lane == 0) sP[r] = (u64)b0 | ((u64)b1 << 32);
        }
    }
    __syncthreads();   // bar1

    // ===== Rank sort: 2 threads per element, 64 compares each =====
    {
        int e = tid & 127, half = tid >> 7;
        u64 my = sKey[e];
        const u64* base = sKey + (half << 6);
        int cnt = 0;
        #pragma unroll 16
        for (int o = 0; o < 64; o++)
            cnt += (base[o] < my);
        sRP[half][e] = (unsigned short)cnt;
    }
    __syncthreads();   // bar2

    if (tid < 128) {
        int rank = (int)sRP[0][tid] + (int)sRP[1][tid];
        sIdxArr[rank] = tid;
    }
    __syncthreads();   // bar3

    // ===== Phase B: permuted rows, 2 threads per row, vectorized =====
    if (tid < 128) {
        int row = tid & 63, half = tid >> 6;
        u64 myP = sP[row];
        u64 w = 0ull;
        const int4* v = (const int4*)(sIdxArr + (half << 6));
        #pragma unroll
        for (int q = 0; q < 16; q++) {
            int4 c4 = v[q];
            int j = q << 2;
            u64 b0 = (c4.x >= 64) ? ((myP >> (c4.x - 64)) & 1ull) : (u64)(c4.x == row);
            u64 b1 = (c4.y >= 64) ? ((myP >> (c4.y - 64)) & 1ull) : (u64)(c4.y == row);
            u64 b2 = (c4.z >= 64) ? ((myP >> (c4.z - 64)) & 1ull) : (u64)(c4.z == row);
            u64 b3 = (c4.w >= 64) ? ((myP >> (c4.w - 64)) & 1ull) : (u64)(c4.w == row);
            w |= (b0 << j) | (b1 << (j + 1)) | (b2 << (j + 2)) | (b3 << (j + 3));
        }
        if (half == 0) rloS[row] = w; else rhiS[row] = w;
    }
    __syncthreads();   // bar4

    // ===== Phase C: GF(2) elimination (warp0, rows 2l/2l+1 per lane, branchless) =====
    if (warp == 0) {
        u64 a0lo = rloS[2 * lane],     a0hi = rhiS[2 * lane];
        u64 a1lo = rloS[2 * lane + 1], a1hi = rhiS[2 * lane + 1];
        u64 pmLo = 0ull, pmHi = 0ull;
        #pragma unroll 1
        for (int i = 0; i < 64; i += 2) {
            int src = i >> 1;
            {   // even step: pivot row i = a0 of lane src
                u64 plo = __shfl_sync(0xFFFFFFFFu, a0lo, src);
                u64 phi = __shfl_sync(0xFFFFFFFFu, a0hi, src);
                int p = plo ? (__ffsll((long long)plo) - 1)
                            : 64 + (__ffsll((long long)phi) - 1);
                if (lane == 0) {
                    sPivArr[i] = p;
                    if (p < 64) pmLo |= 1ull << p; else pmHi |= 1ull << (p - 64);
                }
                int sh = p & 63;
                bool h0 = (((p < 64) ? a0lo : a0hi) >> sh) & 1ull;
                bool h1 = (((p < 64) ? a1lo : a1hi) >> sh) & 1ull;
                if (h0 && lane != src)  { a0lo ^= plo; a0hi ^= phi; }
                if (h1)                 { a1lo ^= plo; a1hi ^= phi; }
            }
            {   // odd step: pivot row i+1 = a1 of lane src
                u64 plo = __shfl_sync(0xFFFFFFFFu, a1lo, src);
                u64 phi = __shfl_sync(0xFFFFFFFFu, a1hi, src);
                int p = plo ? (__ffsll((long long)plo) - 1)
                            : 64 + (__ffsll((long long)phi) - 1);
                if (lane == 0) {
                    sPivArr[i + 1] = p;
                    if (p < 64) pmLo |= 1ull << p; else pmHi |= 1ull << (p - 64);
                }
                int sh = p & 63;
                bool h0 = (((p < 64) ? a0lo : a0hi) >> sh) & 1ull;
                bool h1 = (((p < 64) ? a1lo : a1hi) >> sh) & 1ull;
                if (h0)                 { a0lo ^= plo; a0hi ^= phi; }
                if (h1 && lane != src)  { a1lo ^= plo; a1hi ^= phi; }
            }
        }
        rloS[2 * lane] = a0lo;     rhiS[2 * lane] = a0hi;
        rloS[2 * lane + 1] = a1lo; rhiS[2 * lane + 1] = a1hi;
        if (lane == 0) { sPmLo = pmLo; sPmHi = pmHi; }
    }
    __syncthreads();   // bar5

    // ===== Phase D: idx_mrb + gathers (+ fused sUS / sSm for MRB half) =====
    if (tid < 128) {
        int m;
        if (tid < K) {
            m = sPivArr[tid];
        } else {
            int t = tid - K;
            u64 zlo = ~sPmLo, zhi = ~sPmHi;
            int nlo = __popcll(zlo);
            u64 x; int base;
            if (t < nlo) { x = zlo; base = 0; }
            else         { x = zhi; base = 64; t -= nlo; }
            int pos = 0;
            #pragma unroll
            for (int byteI = 0; byteI < 8; byteI++) {
                u32 bb = (u32)(x >> (byteI * 8)) & 0xFFu;
                int c = __popc(bb);
                if (t < c) {
                    while (t > 0) { bb &= bb - 1; t--; }
                    pos = byteI * 8 + (__ffs(bb) - 1);
                    break;
                }
                t -= c;
            }
            m = base + pos;
        }
        sMrbS[tid] = m;
        int oc = sIdxArr[m];
        float x = sLLR[oc];
        sLlrMrbS[tid] = x;
        sTotS[tid]    = oc;
        if (tid < K) {
            int u = (x > 0.0f) ? 1 : 0;
            sUS[tid] = (unsigned char)u;
            sSm[tid] = u ? -x : x;
        }
    }
    __syncthreads();   // bar6

    // ===== Phase E1: parity partials (2 threads/row), vectorized =====
    if (tid < 128) {
        int row = tid & 63, half = tid >> 6;
        u64 lo = rloS[row], hi = rhiS[row];
        u64 pr = 0ull;
        int p0 = half << 5;
        const int4* v = (const int4*)(sMrbS + 64 + p0);
        #pragma unroll
        for (int q = 0; q < 8; q++) {
            int4 c4 = v[q];
            int p = p0 + (q << 2);
            u64 b0 = (c4.x < 64) ? ((lo >> c4.x) & 1ull) : ((hi >> (c4.x - 64)) & 1ull);
            u64 b1 = (c4.y < 64) ? ((lo >> c4.y) & 1ull) : ((hi >> (c4.y - 64)) & 1ull);
            u64 b2 = (c4.z < 64) ? ((lo >> c4.z) & 1ull) : ((hi >> (c4.z - 64)) & 1ull);
            u64 b3 = (c4.w < 64) ? ((lo >> c4.w) & 1ull) : ((hi >> (c4.w - 64)) & 1ull);
            pr |= (b0 << p) | (b1 << (p + 1)) | (b2 << (p + 2)) | (b3 << (p + 3));
        }
        sPP[half][row] = pr;
    }
    __syncthreads();   // bar7

    // ===== Phase E2: combine + base parity (threads 0..63) =====
    if (tid < K) {
        u64 pr = sPP[0][tid] | sPP[1][tid];
        sProwS[tid] = pr;
        u64 val = sUS[tid] ? pr : 0ull;
        #pragma unroll
        for (int o = 16; o > 0; o >>= 1)
            val ^= __shfl_xor_sync(0xFFFFFFFFu, val, o);
        if (lane == 0) sCparPart[warp] = val;
    }
    __syncthreads();   // bar8

    const u64 cpar = sCparPart[0] ^ sCparPart[1];

    // ===== Phase F: LUT build, parity signs computed inline from cpar =====
    #pragma unroll
    for (int e = 0; e < 8; e++) {
        int idx2 = tid + (e << 8);          // 0..2047, chunk ci = e
        int v = idx2 & 255;
        float s = 0.0f;
        #pragma unroll
        for (int bb = 0; bb < 8; bb++) {
            int p = e * 8 + bb;                       // parity position
            float x = sLlrMrbS[64 + p];
            float sv = ((cpar >> p) & 1ull) ? -x : x; // signed llr
            if ((v >> bb) & 1) s += sv;
        }
        sLUT[idx2] = s;
    }
    __syncthreads();   // bar9

    // ===== Phase G: candidate search =====
    int id, cnt;
    if (tid < 32) { id = tid * 9;              cnt = 9; }
    else          { id = 288 + (tid - 32) * 8; cnt = 8; }

    int pi = 0, pj = 0;
    if (id >= 64 && id < NPAT) decode_pair(id - 64, pi, pj);

    u64 bestKey = (((u64)mono(0.0f)) << 32) | (u32)(NPAT + 1);   // base codeword
    for (int e = 0; e < cnt && id < NPAT; e++) {
        u64 m; float S;
        if (id < 64) { m = sProwS[id];              S = sSm[id]; }
        else         { m = sProwS[pi] ^ sProwS[pj]; S = sSm[pi] + sSm[pj]; }
        #pragma unroll
        for (int cc = 0; cc < 8; cc++)
            S += sLUT[(cc << 8) | ((int)(m >> (cc * 8)) & 0xFF)];
        u64 keyv = (((u64)mono(S)) << 32) | (u32)(NPAT - id);
        if (keyv > bestKey) bestKey = keyv;
        id++;
        if (id == 64)     { pi = 0; pj = 1; }
        else if (id > 64) { pj++; if (pj == 64) { pi++; pj = pi + 1; } }
    }
    #pragma unroll
    for (int o = 16; o > 0; o >>= 1) {
        u64 other = __shfl_xor_sync(0xFFFFFFFFu, bestKey, o);
        if (other > bestKey) bestKey = other;
    }
    if (lane == 0) sRed[warp] = bestKey;
    __syncthreads();   // bar10

    // ===== Phase H: decode winner + emit =====
    if (tid < 128) {
        u64 bk = sRed[0];
        #pragma unroll
        for (int w = 1; w < 8; w++) if (sRed[w] > bk) bk = sRed[w];
        int wid2 = NPAT - (int)(bk & 0xFFFFFFFFull);   // -1 = base
        int fi = -1, fj = -1;
        if (wid2 >= 0) {
            if (wid2 < 64) fi = wid2;
            else           decode_pair(wid2 - 64, fi, fj);
        }
        int j = tid;
        int cj = (j < 64) ? (int)sUS[j] : (int)((cpar >> (j - 64)) & 1ull);
        if (j < 64) {
            if (j == fi) cj ^= 1;
            if (j == fj) cj ^= 1;
        } else {
            int p = j - 64;
            if (fi >= 0) cj ^= (int)((sProwS[fi] >> p) & 1ull);
            if (fj >= 0) cj ^= (int)((sProwS[fj] >> p) & 1ull);
        }
        out[b * N + sTotS[j]] = (float)cj;
    }
}

extern "C" void kernel_launch(void* const* d_in, const int* in_sizes, int n_in,
                              void* d_out, int out_size)
{
    const float* llrs = (const float*)d_in[0];
    const float* gm   = (const float*)d_in[1];
    float* out        = (float*)d_out;
    int bs = in_sizes[0] / N;   // 128
    osd_kernel<<<bs, 256>>>(llrs, gm, out);
}